// round 9
// baseline (speedup 1.0000x reference)
#include <cuda_runtime.h>
#include <math.h>

// BezierRenderer: 16 batches, 512x512, 10 segments.
//  K1 setup <<<16, 256>>>: per-batch segment params + per-tile (64x16) masks.
//  K2 render <<<(8,8,16), 256>>>: PDL. Block = 64x64 px; thread = 16 px
//     (4 rows x float4). One uint4 mask load; fused loop over the UNION of the
//     4 sub-tile masks (masks are conservative, so union is exact).
// Mask layout: g_mask[b*256 + tx*32 + ty]  (ty fastest -> aligned uint4 load).

#define NSEG    10
#define NBATCH  16
#define NTILES  (256 * NBATCH)
#define SIZEI   512

struct SegParams {
    float4 seg[NSEG];        // {vy, vx, dy, dx}
    float  id2[NSEG];
    float  thick, invthick;
};

__device__ SegParams g_params[NBATCH];
__device__ unsigned int g_mask[NTILES];

// ---------------------------------------------------------------------------
// K1: setup. One block per batch: stroke points, segment params, tile masks.
// ---------------------------------------------------------------------------
__global__ void __launch_bounds__(256)
setup_kernel(const float* __restrict__ traj,
             const float* __restrict__ thk)
{
    __shared__ float s_py[NSEG + 1], s_px[NSEG + 1];
    __shared__ float s_vy[NSEG], s_vx[NSEG], s_dy[NSEG], s_dx[NSEG], s_id2[NSEG];
    __shared__ float s_thick;

    const int b   = blockIdx.x;
    const int tid = threadIdx.x;

    if (tid <= NSEG) {
        float sy, sx;
        if (tid < NSEG) {
            const int start[4] = {10, 6, 3, 0};
            sy = 0.f; sx = 0.f;
#pragma unroll
            for (int i = 0; i < 4; i++) {
                float n = (float)(start[i] + tid) - 9.5f;
                float w = 0.75f * expf(-0.125f * n * n);   // exp(-0.5*(n/2)^2)
                sy += traj[b * 8 + i]     * w;
                sx += traj[b * 8 + 4 + i] * w;
            }
        } else {
            sy = traj[b * 8 + 3];
            sx = traj[b * 8 + 7];
        }
        s_py[tid] = sy * 512.f;
        s_px[tid] = sx * 512.f;
    }
    if (tid == 0) {
        float th = 0.f;
#pragma unroll
        for (int k = 0; k < 4; k++) th += thk[b * 4 + k] * 2.f + 0.5f;
        float t2 = 2.f * th;
        s_thick = t2;
        g_params[b].thick    = t2;
        g_params[b].invthick = 1.f / t2;
    }
    __syncthreads();

    if (tid < NSEG) {
        float vy = s_py[tid], vx = s_px[tid];
        float dy = s_py[tid + 1] - vy;
        float dx = s_px[tid + 1] - vx;
        float id2 = 1.f / (dy * dy + dx * dx + 1e-5f);
        s_vy[tid] = vy;  s_vx[tid] = vx;
        s_dy[tid] = dy;  s_dx[tid] = dx;
        s_id2[tid] = id2;
        g_params[b].seg[tid] = make_float4(vy, vx, dy, dx);
        g_params[b].id2[tid] = id2;
    }
    __syncthreads();

    // One tile per thread: tx = tid>>5 (0..7), ty = tid&31 (0..31). Tile 64x16.
    // Center (tx*64+31.5, ty*16+7.5); max px-to-center dist sqrt(31.5^2+7.5^2)
    // = 32.38 < 33. Segment in mask iff dist(center,seg) < thick + 33.
    const float cx = (float)((tid >> 5) << 6) + 31.5f;
    const float cy = (float)((tid & 31) << 4) + 7.5f;
    const float lim = s_thick + 33.0f;
    const float lim2 = lim * lim;

    unsigned int m = 0;
#pragma unroll
    for (int j = 0; j < NSEG; j++) {
        float ay = cy - s_vy[j];
        float ax = cx - s_vx[j];
        float dot = ay * s_dy[j] + ax * s_dx[j];
        float t = fminf(fmaxf(dot * s_id2[j], 0.f), 1.f);
        float ry = fmaf(-t, s_dy[j], ay);
        float rx = fmaf(-t, s_dx[j], ax);
        if (fmaf(ry, ry, rx * rx) < lim2) m |= (1u << j);
    }
    g_mask[b * 256 + tid] = m;    // tid == tx*32 + ty
}

// ---------------------------------------------------------------------------
// K2: render. Block = 64x64 px. Speculative zero stores (independent of K1),
// PDL grid sync, then one fused loop over the union mask: 16 px/thread with
// full ILP (4 rows x 4 cols).
// ---------------------------------------------------------------------------
__global__ void __launch_bounds__(256)
render_kernel(float* __restrict__ out)
{
    const int b   = blockIdx.z;
    const int tid = threadIdx.x;
    const int tx  = blockIdx.x;            // 0..7 (64 px wide)
    const int tyb = blockIdx.y;            // 0..7 (64 px tall)

    const int x  = (tx << 6) + (tid & 15) * 4;
    const int y0 = (tyb << 6) + (tid >> 4);          // rows y0, y0+16, +32, +48
    float* outp0 = out + ((size_t)b << 18) + ((size_t)y0 << 9) + x;

    // Speculative zero fill — independent of setup, issues immediately.
    const float4 z = make_float4(0.f, 0.f, 0.f, 0.f);
    *reinterpret_cast<float4*>(outp0)            = z;
    *reinterpret_cast<float4*>(outp0 + 16 * 512) = z;
    *reinterpret_cast<float4*>(outp0 + 32 * 512) = z;
    *reinterpret_cast<float4*>(outp0 + 48 * 512) = z;

    // Wait for setup_kernel's results (PDL).
    cudaGridDependencySynchronize();

    const uint4 mv = __ldg(reinterpret_cast<const uint4*>(
        &g_mask[b * 256 + tx * 32 + tyb * 4]));
    unsigned int mask = mv.x | mv.y | mv.z | mv.w;   // union: exact (masks conservative)
    if (mask == 0) return;

    const SegParams* sp = &g_params[b];
    const float thick    = __ldg(&sp->thick);
    const float invthick = __ldg(&sp->invthick);

    const float yf = (float)y0;
    const float x0 = (float)x;

    float m[4][4];
#pragma unroll
    for (int r = 0; r < 4; r++)
#pragma unroll
        for (int c = 0; c < 4; c++) m[r][c] = 1e30f;

    while (mask) {
        const int j = __ffs(mask) - 1;
        mask &= mask - 1;

        const float4 s  = __ldg(&sp->seg[j]);   // {vy, vx, dy, dx}
        const float ij  = __ldg(&sp->id2[j]);
        const float vjx = s.y, djy = s.z, djx = s.w;

        float ay[4], cyd[4];
#pragma unroll
        for (int r = 0; r < 4; r++) {
            ay[r]  = (yf + (float)(16 * r)) - s.x;
            cyd[r] = ay[r] * djy;
        }

#pragma unroll
        for (int c = 0; c < 4; c++) {
            const float pvx = (x0 + (float)c) - vjx;
#pragma unroll
            for (int r = 0; r < 4; r++) {
                float dot = fmaf(pvx, djx, cyd[r]);
                float t   = fminf(fmaxf(dot * ij, 0.f), 1.f);
                float ry  = fmaf(-t, djy, ay[r]);
                float rx  = fmaf(-t, djx, pvx);
                m[r][c] = fminf(m[r][c], fmaf(ry, ry, rx * rx));
            }
        }
    }

#pragma unroll
    for (int r = 0; r < 4; r++) {
        float4 res;
        res.x = fminf(fmaxf((thick - sqrtf(m[r][0])) * invthick, 0.f), 1.f);
        res.y = fminf(fmaxf((thick - sqrtf(m[r][1])) * invthick, 0.f), 1.f);
        res.z = fminf(fmaxf((thick - sqrtf(m[r][2])) * invthick, 0.f), 1.f);
        res.w = fminf(fmaxf((thick - sqrtf(m[r][3])) * invthick, 0.f), 1.f);
        *reinterpret_cast<float4*>(outp0 + r * 16 * 512) = res;
    }
}

extern "C" void kernel_launch(void* const* d_in, const int* in_sizes, int n_in,
                              void* d_out, int out_size)
{
    const float* traj = (const float*)d_in[0];   // (16, 2, 4)
    const float* thk  = (const float*)d_in[1];   // (16, 1, 4)
    float* out = (float*)d_out;                  // (16, 512, 512)

    setup_kernel<<<NBATCH, 256>>>(traj, thk);

    // Render with Programmatic Dependent Launch: overlaps with setup; the
    // kernel waits (cudaGridDependencySynchronize) only before reading
    // setup's outputs.
    cudaLaunchConfig_t cfg = {};
    cfg.gridDim  = dim3(8, 8, NBATCH);           // 1024 blocks
    cfg.blockDim = dim3(256, 1, 1);
    cfg.dynamicSmemBytes = 0;
    cfg.stream = 0;

    cudaLaunchAttribute attr[1];
    attr[0].id = cudaLaunchAttributeProgrammaticStreamSerialization;
    attr[0].val.programmaticStreamSerializationAllowed = 1;
    cfg.attrs = attr;
    cfg.numAttrs = 1;

    cudaLaunchKernelEx(&cfg, render_kernel, out);
}